// round 13
// baseline (speedup 1.0000x reference)
#include <cuda_runtime.h>
#include <cuda_fp16.h>
#include <mma.h>
#include <math.h>
#include <cstdint>

using namespace nvcuda;

#define S_LEN 2048
#define HID   4096
#define NHEAD 32
#define INTER 11008

// ---------------- scratch buffers ----------------
__device__ __half g_Wq[HID * HID];
__device__ __half g_Wk[HID * HID];
__device__ __half g_Wv[HID * HID];
__device__ __half g_Wo[HID * HID];
__device__ __half g_Wg[INTER * HID];
__device__ __half g_Wu[INTER * HID];
__device__ __half g_Wd[HID * INTER];

__device__ __half g_Xn [S_LEN * HID];
__device__ __half g_Qp [S_LEN * HID];
__device__ __half g_Kp [S_LEN * HID];
__device__ __half g_Vh [S_LEN * HID];
__device__ __half g_Qh [S_LEN * HID];
__device__ __half g_Kh [S_LEN * HID];
__device__ __half g_AttnH[S_LEN * HID];
__device__ float  g_H1 [S_LEN * HID];
__device__ __half g_Xn2[S_LEN * HID];
__device__ __half g_Gh [S_LEN * INTER];
__device__ __half g_Uh [S_LEN * INTER];
__device__ __half g_Mh [S_LEN * INTER];

// ---------------- elementwise ----------------
__global__ void f2h_kernel(const float* __restrict__ in, __half* __restrict__ out, long long n) {
    long long i = ((long long)blockIdx.x * blockDim.x + threadIdx.x) * 4;
    long long stride = (long long)gridDim.x * blockDim.x * 4;
    for (; i < n; i += stride) {
        float4 v = *(const float4*)(in + i);
        *(__half2*)(out + i)     = __floats2half2_rn(v.x, v.y);
        *(__half2*)(out + i + 2) = __floats2half2_rn(v.z, v.w);
    }
}

__global__ void rmsnorm_kernel(const float* __restrict__ x, const float* __restrict__ w,
                               __half* __restrict__ out) {
    int row = blockIdx.x;
    const float* xr = x + (long long)row * HID;
    float ss = 0.f;
    for (int c = threadIdx.x * 4; c < HID; c += blockDim.x * 4) {
        float4 v = *(const float4*)(xr + c);
        ss += v.x * v.x + v.y * v.y + v.z * v.z + v.w * v.w;
    }
#pragma unroll
    for (int o = 16; o > 0; o >>= 1) ss += __shfl_xor_sync(0xffffffffu, ss, o);
    __shared__ float sh[8];
    __shared__ float inv_s;
    if ((threadIdx.x & 31) == 0) sh[threadIdx.x >> 5] = ss;
    __syncthreads();
    if (threadIdx.x == 0) {
        float t = 0.f;
        for (int i = 0; i < 8; i++) t += sh[i];
        inv_s = rsqrtf(t / (float)HID + 1e-5f);
    }
    __syncthreads();
    float inv = inv_s;
    __half* orow = out + (long long)row * HID;
    for (int c = threadIdx.x * 4; c < HID; c += blockDim.x * 4) {
        float4 v  = *(const float4*)(xr + c);
        float4 wv = *(const float4*)(w + c);
        *(__half2*)(orow + c)     = __floats2half2_rn(v.x * inv * wv.x, v.y * inv * wv.y);
        *(__half2*)(orow + c + 2) = __floats2half2_rn(v.z * inv * wv.z, v.w * inv * wv.w);
    }
}

__global__ void rope_kernel(const __half* __restrict__ Qp, const __half* __restrict__ Kp,
                            const int* __restrict__ pos,
                            __half* __restrict__ Qh, __half* __restrict__ Kh) {
    int t = blockIdx.x * blockDim.x + threadIdx.x;
    if (t >= S_LEN * 2048) return;
    int s = t >> 11;
    int r = t & 2047;
    int h = r >> 6;
    int j = r & 63;
    float p = (float)pos[s];
    float invf = exp2f(-(float)j * 0.20762050593046014f);  // 10000^(-j/64)
    float ang = p * invf;
    float c, sn;
    sincosf(ang, &sn, &c);
    long long base = (long long)s * HID + h * 128 + j;
    float q1 = __half2float(Qp[base]), q2 = __half2float(Qp[base + 64]);
    Qh[base]      = __float2half(q1 * c - q2 * sn);
    Qh[base + 64] = __float2half(q2 * c + q1 * sn);
    float k1 = __half2float(Kp[base]), k2 = __half2float(Kp[base + 64]);
    Kh[base]      = __float2half(k1 * c - k2 * sn);
    Kh[base + 64] = __float2half(k2 * c + k1 * sn);
}

__global__ void silu_kernel(const __half* __restrict__ g, const __half* __restrict__ u,
                            __half* __restrict__ out, long long n) {
    long long i = ((long long)blockIdx.x * blockDim.x + threadIdx.x) * 8;
    long long stride = (long long)gridDim.x * blockDim.x * 8;
    for (; i < n; i += stride) {
        int4 gv = *(const int4*)(g + i);
        int4 uv = *(const int4*)(u + i);
        int4 ov;
        const __half2* gh = (const __half2*)&gv;
        const __half2* uh = (const __half2*)&uv;
        __half2* oh = (__half2*)&ov;
#pragma unroll
        for (int q = 0; q < 4; q++) {
            float2 gf = __half22float2(gh[q]);
            float2 uf = __half22float2(uh[q]);
            float m0 = gf.x / (1.f + __expf(-gf.x)) * uf.x;
            float m1 = gf.y / (1.f + __expf(-gf.y)) * uf.y;
            oh[q] = __floats2half2_rn(m0, m1);
        }
        *(int4*)(out + i) = ov;
    }
}

// ---------------- flash attention (wmma, fused) ----------------
#define FA_QR 64
#define FA_KC 128
#define FA_SMEM 135680

__global__ __launch_bounds__(256) void flash_kernel(
    const __half* __restrict__ Q, const __half* __restrict__ K,
    const __half* __restrict__ V, __half* __restrict__ O) {
    extern __shared__ char sm[];
    __half* Qs  = (__half*)(sm);
    __half* KVs = (__half*)(sm + 17408);
    float*  Ss  = (float*)(sm + 52224);
    __half* Ps  = (__half*)(sm + 84992);
    float*  Os  = (float*)(sm + 102400);
    float*  mrow = (float*)(sm + 135168);
    float*  lrow = (float*)(sm + 135424);

    const int qb = blockIdx.x, h = blockIdx.y;
    const int tid = threadIdx.x, warp = tid >> 5, lane = tid & 31;
    const int rb = warp & 3, ch = warp >> 2;
    const int q0 = qb * FA_QR;
    const int colh = h * 128;
    const __half2 qscale = __half2half2(__float2half(0.08838834764831845f));

    if (tid < FA_QR) { mrow[tid] = -1e30f; lrow[tid] = 0.f; }
    for (int i = tid; i < FA_QR * 128 / 4; i += 256)
        ((float4*)Os)[i] = make_float4(0.f, 0.f, 0.f, 0.f);

    for (int it = tid; it < FA_QR * 16; it += 256) {
        int r = it >> 4, c = it & 15;
        int4 v = *(const int4*)(Q + (long long)(q0 + r) * HID + colh + c * 8);
        __half2* hv = (__half2*)&v;
        hv[0] = __hmul2(hv[0], qscale); hv[1] = __hmul2(hv[1], qscale);
        hv[2] = __hmul2(hv[2], qscale); hv[3] = __hmul2(hv[3], qscale);
        *(int4*)(Qs + r * 136 + c * 8) = v;
    }
    __syncthreads();

    const int kb_max = (q0 + FA_QR - 1) >> 7;
    for (int kb = 0; kb <= kb_max; kb++) {
        for (int it = tid; it < FA_KC * 16; it += 256) {
            int r = it >> 4, c = it & 15;
            *(int4*)(KVs + r * 136 + c * 8) =
                *(const int4*)(K + (long long)(kb * FA_KC + r) * HID + colh + c * 8);
        }
        __syncthreads();
        for (int nf = ch * 4; nf < ch * 4 + 4; nf++) {
            wmma::fragment<wmma::accumulator, 16, 16, 16, float> acc;
            wmma::fill_fragment(acc, 0.f);
#pragma unroll
            for (int ks = 0; ks < 8; ks++) {
                wmma::fragment<wmma::matrix_a, 16, 16, 16, __half, wmma::row_major> af;
                wmma::fragment<wmma::matrix_b, 16, 16, 16, __half, wmma::col_major> bf;
                wmma::load_matrix_sync(af, Qs + rb * 16 * 136 + ks * 16, 136);
                wmma::load_matrix_sync(bf, KVs + nf * 16 * 136 + ks * 16, 136);
                wmma::mma_sync(acc, af, bf, acc);
            }
            wmma::store_matrix_sync(Ss + rb * 16 * 128 + nf * 16, acc, 128, wmma::mem_row_major);
        }
        __syncthreads();
        for (int it = tid; it < FA_KC * 16; it += 256) {
            int r = it >> 4, c = it & 15;
            *(int4*)(KVs + r * 136 + c * 8) =
                *(const int4*)(V + (long long)(kb * FA_KC + r) * HID + colh + c * 8);
        }
        for (int rr = 0; rr < 8; rr++) {
            int r = warp * 8 + rr;
            int grow = q0 + r;
            float s0 = Ss[r * 128 + lane];
            float s1 = Ss[r * 128 + lane + 32];
            float s2 = Ss[r * 128 + lane + 64];
            float s3 = Ss[r * 128 + lane + 96];
            int gc = kb * FA_KC + lane;
            if (gc      > grow) s0 = -1e30f;
            if (gc + 32 > grow) s1 = -1e30f;
            if (gc + 64 > grow) s2 = -1e30f;
            if (gc + 96 > grow) s3 = -1e30f;
            float mx = fmaxf(fmaxf(s0, s1), fmaxf(s2, s3));
#pragma unroll
            for (int o = 16; o > 0; o >>= 1) mx = fmaxf(mx, __shfl_xor_sync(0xffffffffu, mx, o));
            float mold = mrow[r];
            float mnew = fmaxf(mold, mx);
            float alpha = __expf(mold - mnew);
            float e0 = __expf(s0 - mnew), e1 = __expf(s1 - mnew);
            float e2 = __expf(s2 - mnew), e3 = __expf(s3 - mnew);
            float sum = e0 + e1 + e2 + e3;
#pragma unroll
            for (int o = 16; o > 0; o >>= 1) sum += __shfl_xor_sync(0xffffffffu, sum, o);
            if (lane == 0) { mrow[r] = mnew; lrow[r] = lrow[r] * alpha + sum; }
            Ps[r * 136 + lane]      = __float2half(e0);
            Ps[r * 136 + lane + 32] = __float2half(e1);
            Ps[r * 136 + lane + 64] = __float2half(e2);
            Ps[r * 136 + lane + 96] = __float2half(e3);
            Os[r * 128 + lane]      *= alpha;
            Os[r * 128 + lane + 32] *= alpha;
            Os[r * 128 + lane + 64] *= alpha;
            Os[r * 128 + lane + 96] *= alpha;
        }
        __syncthreads();
        for (int nf = 0; nf < 4; nf++) {
            int ncol = ch * 64 + nf * 16;
            wmma::fragment<wmma::accumulator, 16, 16, 16, float> acc;
            wmma::load_matrix_sync(acc, Os + rb * 16 * 128 + ncol, 128, wmma::mem_row_major);
#pragma unroll
            for (int ks = 0; ks < 8; ks++) {
                wmma::fragment<wmma::matrix_a, 16, 16, 16, __half, wmma::row_major> af;
                wmma::fragment<wmma::matrix_b, 16, 16, 16, __half, wmma::row_major> bf;
                wmma::load_matrix_sync(af, Ps + rb * 16 * 136 + ks * 16, 136);
                wmma::load_matrix_sync(bf, KVs + ks * 16 * 136 + ncol, 136);
                wmma::mma_sync(acc, af, bf, acc);
            }
            wmma::store_matrix_sync(Os + rb * 16 * 128 + ncol, acc, 128, wmma::mem_row_major);
        }
        __syncthreads();
    }

    for (int rr = 0; rr < 8; rr++) {
        int r = warp * 8 + rr;
        float inv = 1.f / lrow[r];
        __half* orow = O + (long long)(q0 + r) * HID + colh;
        orow[lane]      = __float2half(Os[r * 128 + lane] * inv);
        orow[lane + 32] = __float2half(Os[r * 128 + lane + 32] * inv);
        orow[lane + 64] = __float2half(Os[r * 128 + lane + 64] * inv);
        orow[lane + 96] = __float2half(Os[r * 128 + lane + 96] * inv);
    }
}

// ---------------- cp.async multistage wmma GEMM, 128x128 CTA / 64x64 warp, 2 CTA/SM ----
// C[M,N] = A[M,K] * B[N,K]^T, fp16 in, fp32 accum.
// OUT: 0 = float, 1 = float + residual, 2 = half.
#define GBM 128
#define GBN 128
#define GBK 32
#define GROWL 40                           // halves per smem row (32 + 8 pad)
#define GA_BYTES (GBM * GROWL * 2)         // 10240
#define GB_BYTES (GBN * GROWL * 2)         // 10240
#define GSTAGE_BYTES (GA_BYTES + GB_BYTES) // 20480
#define GSTAGES 4
#define GEMM_SMEM (GSTAGES * GSTAGE_BYTES) // 81920

__device__ __forceinline__ uint32_t smem_u32(const void* p) {
    uint32_t a;
    asm("{ .reg .u64 t; cvta.to.shared.u64 t, %1; cvt.u32.u64 %0, t; }" : "=r"(a) : "l"(p));
    return a;
}
__device__ __forceinline__ void cpa16(uint32_t s, const void* g) {
    asm volatile("cp.async.cg.shared.global [%0], [%1], 16;" :: "r"(s), "l"(g));
}

template <int OUT>
__global__ __launch_bounds__(128, 2) void gemm_cp(
    const __half* __restrict__ A, const __half* __restrict__ B, void* __restrict__ Cv,
    const float* __restrict__ res, int M, int N, int K) {
    extern __shared__ char smem[];
    const int tid = threadIdx.x;
    const int warp = tid >> 5, lane = tid & 31;
    const int wm = warp & 1, wn = warp >> 1;          // 2 x 2 warp grid, 64x64 tiles
    const int m0 = blockIdx.y * GBM, n0 = blockIdx.x * GBN;
    const int nk = K / GBK;

    const int lr = tid;                 // 0..127: one A row + one B row per thread
    const uint32_t sbase = smem_u32(smem);

    auto load_tile = [&](int st, int kt) {
        const int k0 = kt * GBK;
        uint32_t sa = sbase + st * GSTAGE_BYTES + lr * (GROWL * 2);
        const __half* ga = A + (long long)(m0 + lr) * K + k0;
        cpa16(sa,      ga);
        cpa16(sa + 16, ga + 8);
        cpa16(sa + 32, ga + 16);
        cpa16(sa + 48, ga + 24);
        uint32_t sb = sa + GA_BYTES;
        const __half* gb = B + (long long)(n0 + lr) * K + k0;
        cpa16(sb,      gb);
        cpa16(sb + 16, gb + 8);
        cpa16(sb + 32, gb + 16);
        cpa16(sb + 48, gb + 24);
    };

#pragma unroll
    for (int s = 0; s < GSTAGES - 1; s++) {
        load_tile(s, s);
        asm volatile("cp.async.commit_group;" ::: "memory");
    }

    wmma::fragment<wmma::accumulator, 16, 16, 16, float> cf[4][4];
#pragma unroll
    for (int i = 0; i < 4; i++)
#pragma unroll
        for (int j = 0; j < 4; j++) wmma::fill_fragment(cf[i][j], 0.f);

    for (int kt = 0; kt < nk; kt++) {
        asm volatile("cp.async.wait_group %0;" :: "n"(GSTAGES - 2) : "memory");
        __syncthreads();
        const int buf = kt % GSTAGES;
        const __half* As = (const __half*)(smem + buf * GSTAGE_BYTES);
        const __half* Bs = As + GBM * GROWL;
#pragma unroll
        for (int kk = 0; kk < 2; kk++) {
            wmma::fragment<wmma::matrix_a, 16, 16, 16, __half, wmma::row_major> af[4];
#pragma unroll
            for (int i = 0; i < 4; i++)
                wmma::load_matrix_sync(af[i], As + (wm * 64 + i * 16) * GROWL + kk * 16, GROWL);
            wmma::fragment<wmma::matrix_b, 16, 16, 16, __half, wmma::col_major> bf[4];
#pragma unroll
            for (int j = 0; j < 4; j++)
                wmma::load_matrix_sync(bf[j], Bs + (wn * 64 + j * 16) * GROWL + kk * 16, GROWL);
#pragma unroll
            for (int i = 0; i < 4; i++)
#pragma unroll
                for (int j = 0; j < 4; j++) wmma::mma_sync(cf[i][j], af[i], bf[j], cf[i][j]);
        }
        const int nt = kt + GSTAGES - 1;
        if (nt < nk) load_tile(nt % GSTAGES, nt);
        asm volatile("cp.async.commit_group;" ::: "memory");
    }
    asm volatile("cp.async.wait_group 0;" ::: "memory");
    __syncthreads();

    // epilogue: per-warp 64x64 fp32 staging in smem (4 warps x 16KB = 64KB <= 80KB)
    float* Cw = (float*)smem + warp * 64 * 64;
#pragma unroll
    for (int i = 0; i < 4; i++)
#pragma unroll
        for (int j = 0; j < 4; j++)
            wmma::store_matrix_sync(Cw + (i * 16) * 64 + j * 16, cf[i][j], 64, wmma::mem_row_major);
    __syncwarp();

    const int gm = m0 + wm * 64;
    const int gn = n0 + wn * 64;
    for (int it = lane; it < 64 * 16; it += 32) {
        int r = it >> 4, c4 = it & 15;
        float4 v = *(const float4*)(Cw + r * 64 + c4 * 4);
        long long grow = (long long)(gm + r) * N + gn + c4 * 4;
        if (OUT == 1) {
            float4 rv = *(const float4*)(res + grow);
            v.x += rv.x; v.y += rv.y; v.z += rv.z; v.w += rv.w;
        }
        if (OUT == 2) {
            __half2 h0 = __floats2half2_rn(v.x, v.y);
            __half2 h1 = __floats2half2_rn(v.z, v.w);
            uint2 o;
            o.x = *(uint32_t*)&h0; o.y = *(uint32_t*)&h1;
            *(uint2*)((__half*)Cv + grow) = o;
        } else {
            *(float4*)((float*)Cv + grow) = v;
        }
    }
}

// ---------------- host ----------------
extern "C" void kernel_launch(void* const* d_in, const int* in_sizes, int n_in,
                              void* d_out, int out_size) {
    const float* hidden = (const float*)d_in[0];
    const int*   pos    = (const int*)d_in[1];
    const float* ln1    = (const float*)d_in[2];
    const float* ln2    = (const float*)d_in[3];
    const float* wq     = (const float*)d_in[4];
    const float* wk     = (const float*)d_in[5];
    const float* wv     = (const float*)d_in[6];
    const float* wo     = (const float*)d_in[7];
    const float* wg     = (const float*)d_in[8];
    const float* wu     = (const float*)d_in[9];
    const float* wd     = (const float*)d_in[10];
    float* out = (float*)d_out;

    void *pWq, *pWk, *pWv, *pWo, *pWg, *pWu, *pWd;
    void *pXn, *pQp, *pKp, *pVh, *pQh, *pKh, *pAh, *pH1, *pXn2, *pGh, *pUh, *pMh;
    cudaGetSymbolAddress(&pWq, g_Wq);   cudaGetSymbolAddress(&pWk, g_Wk);
    cudaGetSymbolAddress(&pWv, g_Wv);   cudaGetSymbolAddress(&pWo, g_Wo);
    cudaGetSymbolAddress(&pWg, g_Wg);   cudaGetSymbolAddress(&pWu, g_Wu);
    cudaGetSymbolAddress(&pWd, g_Wd);
    cudaGetSymbolAddress(&pXn, g_Xn);   cudaGetSymbolAddress(&pQp, g_Qp);
    cudaGetSymbolAddress(&pKp, g_Kp);   cudaGetSymbolAddress(&pVh, g_Vh);
    cudaGetSymbolAddress(&pQh, g_Qh);   cudaGetSymbolAddress(&pKh, g_Kh);
    cudaGetSymbolAddress(&pAh, g_AttnH); cudaGetSymbolAddress(&pH1, g_H1);
    cudaGetSymbolAddress(&pXn2, g_Xn2); cudaGetSymbolAddress(&pGh, g_Gh);
    cudaGetSymbolAddress(&pUh, g_Uh);   cudaGetSymbolAddress(&pMh, g_Mh);

    cudaFuncSetAttribute(flash_kernel, cudaFuncAttributeMaxDynamicSharedMemorySize, FA_SMEM);
    cudaFuncSetAttribute(gemm_cp<0>, cudaFuncAttributeMaxDynamicSharedMemorySize, GEMM_SMEM);
    cudaFuncSetAttribute(gemm_cp<1>, cudaFuncAttributeMaxDynamicSharedMemorySize, GEMM_SMEM);
    cudaFuncSetAttribute(gemm_cp<2>, cudaFuncAttributeMaxDynamicSharedMemorySize, GEMM_SMEM);

    const long long nHH = (long long)HID * HID;
    const long long nIH = (long long)INTER * HID;
    const long long nSI = (long long)S_LEN * INTER;

    // 1: rmsnorm, 2-3: f2h q/k, 4-5: gemm Q/K (GEMM early for ncu capture)
    rmsnorm_kernel<<<S_LEN, 256>>>(hidden, ln1, (__half*)pXn);
    f2h_kernel<<<8192, 256>>>(wq, (__half*)pWq, nHH);
    f2h_kernel<<<8192, 256>>>(wk, (__half*)pWk, nHH);
    gemm_cp<2><<<dim3(HID / GBN, S_LEN / GBM), 128, GEMM_SMEM>>>(
        (const __half*)pXn, (const __half*)pWq, pQp, nullptr, S_LEN, HID, HID);
    gemm_cp<2><<<dim3(HID / GBN, S_LEN / GBM), 128, GEMM_SMEM>>>(
        (const __half*)pXn, (const __half*)pWk, pKp, nullptr, S_LEN, HID, HID);
    f2h_kernel<<<8192, 256>>>(wv, (__half*)pWv, nHH);
    gemm_cp<2><<<dim3(HID / GBN, S_LEN / GBM), 128, GEMM_SMEM>>>(
        (const __half*)pXn, (const __half*)pWv, pVh, nullptr, S_LEN, HID, HID);

    rope_kernel<<<(S_LEN * 2048 + 255) / 256, 256>>>(
        (const __half*)pQp, (const __half*)pKp, pos, (__half*)pQh, (__half*)pKh);
    f2h_kernel<<<8192, 256>>>(wo, (__half*)pWo, nHH);

    flash_kernel<<<dim3(S_LEN / FA_QR, NHEAD), 256, FA_SMEM>>>(
        (const __half*)pQh, (const __half*)pKh, (const __half*)pVh, (__half*)pAh);

    gemm_cp<1><<<dim3(HID / GBN, S_LEN / GBM), 128, GEMM_SMEM>>>(
        (const __half*)pAh, (const __half*)pWo, pH1, hidden, S_LEN, HID, HID);

    f2h_kernel<<<8192, 256>>>(wg, (__half*)pWg, nIH);
    f2h_kernel<<<8192, 256>>>(wu, (__half*)pWu, nIH);
    rmsnorm_kernel<<<S_LEN, 256>>>((const float*)pH1, ln2, (__half*)pXn2);
    gemm_cp<2><<<dim3(INTER / GBN, S_LEN / GBM), 128, GEMM_SMEM>>>(
        (const __half*)pXn2, (const __half*)pWg, pGh, nullptr, S_LEN, INTER, HID);
    gemm_cp<2><<<dim3(INTER / GBN, S_LEN / GBM), 128, GEMM_SMEM>>>(
        (const __half*)pXn2, (const __half*)pWu, pUh, nullptr, S_LEN, INTER, HID);
    f2h_kernel<<<8192, 256>>>(wd, (__half*)pWd, nIH);
    silu_kernel<<<4096, 256>>>((const __half*)pGh, (const __half*)pUh, (__half*)pMh, nSI);
    gemm_cp<1><<<dim3(HID / GBN, S_LEN / GBM), 128, GEMM_SMEM>>>(
        (const __half*)pMh, (const __half*)pWd, out, (const float*)pH1, S_LEN, HID, INTER);
}

// round 14
// speedup vs baseline: 1.0122x; 1.0122x over previous
#include <cuda_runtime.h>
#include <cuda_fp16.h>
#include <mma.h>
#include <math.h>
#include <cstdint>

using namespace nvcuda;

#define S_LEN 2048
#define HID   4096
#define NHEAD 32
#define INTER 11008

// ---------------- scratch buffers ----------------
__device__ __half g_Wq[HID * HID];
__device__ __half g_Wk[HID * HID];
__device__ __half g_Wv[HID * HID];
__device__ __half g_Wo[HID * HID];
__device__ __half g_Wg[INTER * HID];
__device__ __half g_Wu[INTER * HID];
__device__ __half g_Wd[HID * INTER];

__device__ __half g_Xn [S_LEN * HID];
__device__ __half g_Qp [S_LEN * HID];
__device__ __half g_Kp [S_LEN * HID];
__device__ __half g_Vh [S_LEN * HID];
__device__ __half g_Qh [S_LEN * HID];
__device__ __half g_Kh [S_LEN * HID];
__device__ __half g_AttnH[S_LEN * HID];
__device__ float  g_H1 [S_LEN * HID];
__device__ __half g_Xn2[S_LEN * HID];
__device__ __half g_Gh [S_LEN * INTER];
__device__ __half g_Uh [S_LEN * INTER];
__device__ __half g_Mh [S_LEN * INTER];

// ---------------- elementwise ----------------
__global__ void f2h_kernel(const float* __restrict__ in, __half* __restrict__ out, long long n) {
    long long i = ((long long)blockIdx.x * blockDim.x + threadIdx.x) * 4;
    long long stride = (long long)gridDim.x * blockDim.x * 4;
    for (; i < n; i += stride) {
        float4 v = *(const float4*)(in + i);
        *(__half2*)(out + i)     = __floats2half2_rn(v.x, v.y);
        *(__half2*)(out + i + 2) = __floats2half2_rn(v.z, v.w);
    }
}

__global__ void rmsnorm_kernel(const float* __restrict__ x, const float* __restrict__ w,
                               __half* __restrict__ out) {
    int row = blockIdx.x;
    const float* xr = x + (long long)row * HID;
    float ss = 0.f;
    for (int c = threadIdx.x * 4; c < HID; c += blockDim.x * 4) {
        float4 v = *(const float4*)(xr + c);
        ss += v.x * v.x + v.y * v.y + v.z * v.z + v.w * v.w;
    }
#pragma unroll
    for (int o = 16; o > 0; o >>= 1) ss += __shfl_xor_sync(0xffffffffu, ss, o);
    __shared__ float sh[8];
    __shared__ float inv_s;
    if ((threadIdx.x & 31) == 0) sh[threadIdx.x >> 5] = ss;
    __syncthreads();
    if (threadIdx.x == 0) {
        float t = 0.f;
        for (int i = 0; i < 8; i++) t += sh[i];
        inv_s = rsqrtf(t / (float)HID + 1e-5f);
    }
    __syncthreads();
    float inv = inv_s;
    __half* orow = out + (long long)row * HID;
    for (int c = threadIdx.x * 4; c < HID; c += blockDim.x * 4) {
        float4 v  = *(const float4*)(xr + c);
        float4 wv = *(const float4*)(w + c);
        *(__half2*)(orow + c)     = __floats2half2_rn(v.x * inv * wv.x, v.y * inv * wv.y);
        *(__half2*)(orow + c + 2) = __floats2half2_rn(v.z * inv * wv.z, v.w * inv * wv.w);
    }
}

__global__ void rope_kernel(const __half* __restrict__ Qp, const __half* __restrict__ Kp,
                            const int* __restrict__ pos,
                            __half* __restrict__ Qh, __half* __restrict__ Kh) {
    int t = blockIdx.x * blockDim.x + threadIdx.x;
    if (t >= S_LEN * 2048) return;
    int s = t >> 11;
    int r = t & 2047;
    int h = r >> 6;
    int j = r & 63;
    float p = (float)pos[s];
    float invf = exp2f(-(float)j * 0.20762050593046014f);  // 10000^(-j/64)
    float ang = p * invf;
    float c, sn;
    sincosf(ang, &sn, &c);
    long long base = (long long)s * HID + h * 128 + j;
    float q1 = __half2float(Qp[base]), q2 = __half2float(Qp[base + 64]);
    Qh[base]      = __float2half(q1 * c - q2 * sn);
    Qh[base + 64] = __float2half(q2 * c + q1 * sn);
    float k1 = __half2float(Kp[base]), k2 = __half2float(Kp[base + 64]);
    Kh[base]      = __float2half(k1 * c - k2 * sn);
    Kh[base + 64] = __float2half(k2 * c + k1 * sn);
}

__global__ void silu_kernel(const __half* __restrict__ g, const __half* __restrict__ u,
                            __half* __restrict__ out, long long n) {
    long long i = ((long long)blockIdx.x * blockDim.x + threadIdx.x) * 8;
    long long stride = (long long)gridDim.x * blockDim.x * 8;
    for (; i < n; i += stride) {
        int4 gv = *(const int4*)(g + i);
        int4 uv = *(const int4*)(u + i);
        int4 ov;
        const __half2* gh = (const __half2*)&gv;
        const __half2* uh = (const __half2*)&uv;
        __half2* oh = (__half2*)&ov;
#pragma unroll
        for (int q = 0; q < 4; q++) {
            float2 gf = __half22float2(gh[q]);
            float2 uf = __half22float2(uh[q]);
            float m0 = gf.x / (1.f + __expf(-gf.x)) * uf.x;
            float m1 = gf.y / (1.f + __expf(-gf.y)) * uf.y;
            oh[q] = __floats2half2_rn(m0, m1);
        }
        *(int4*)(out + i) = ov;
    }
}

// ---------------- flash attention (wmma, fused) ----------------
#define FA_QR 64
#define FA_KC 128
#define FA_SMEM 135680

__global__ __launch_bounds__(256) void flash_kernel(
    const __half* __restrict__ Q, const __half* __restrict__ K,
    const __half* __restrict__ V, __half* __restrict__ O) {
    extern __shared__ char sm[];
    __half* Qs  = (__half*)(sm);
    __half* KVs = (__half*)(sm + 17408);
    float*  Ss  = (float*)(sm + 52224);
    __half* Ps  = (__half*)(sm + 84992);
    float*  Os  = (float*)(sm + 102400);
    float*  mrow = (float*)(sm + 135168);
    float*  lrow = (float*)(sm + 135424);

    const int qb = blockIdx.x, h = blockIdx.y;
    const int tid = threadIdx.x, warp = tid >> 5, lane = tid & 31;
    const int rb = warp & 3, ch = warp >> 2;
    const int q0 = qb * FA_QR;
    const int colh = h * 128;
    const __half2 qscale = __half2half2(__float2half(0.08838834764831845f));

    if (tid < FA_QR) { mrow[tid] = -1e30f; lrow[tid] = 0.f; }
    for (int i = tid; i < FA_QR * 128 / 4; i += 256)
        ((float4*)Os)[i] = make_float4(0.f, 0.f, 0.f, 0.f);

    for (int it = tid; it < FA_QR * 16; it += 256) {
        int r = it >> 4, c = it & 15;
        int4 v = *(const int4*)(Q + (long long)(q0 + r) * HID + colh + c * 8);
        __half2* hv = (__half2*)&v;
        hv[0] = __hmul2(hv[0], qscale); hv[1] = __hmul2(hv[1], qscale);
        hv[2] = __hmul2(hv[2], qscale); hv[3] = __hmul2(hv[3], qscale);
        *(int4*)(Qs + r * 136 + c * 8) = v;
    }
    __syncthreads();

    const int kb_max = (q0 + FA_QR - 1) >> 7;
    for (int kb = 0; kb <= kb_max; kb++) {
        for (int it = tid; it < FA_KC * 16; it += 256) {
            int r = it >> 4, c = it & 15;
            *(int4*)(KVs + r * 136 + c * 8) =
                *(const int4*)(K + (long long)(kb * FA_KC + r) * HID + colh + c * 8);
        }
        __syncthreads();
        for (int nf = ch * 4; nf < ch * 4 + 4; nf++) {
            wmma::fragment<wmma::accumulator, 16, 16, 16, float> acc;
            wmma::fill_fragment(acc, 0.f);
#pragma unroll
            for (int ks = 0; ks < 8; ks++) {
                wmma::fragment<wmma::matrix_a, 16, 16, 16, __half, wmma::row_major> af;
                wmma::fragment<wmma::matrix_b, 16, 16, 16, __half, wmma::col_major> bf;
                wmma::load_matrix_sync(af, Qs + rb * 16 * 136 + ks * 16, 136);
                wmma::load_matrix_sync(bf, KVs + nf * 16 * 136 + ks * 16, 136);
                wmma::mma_sync(acc, af, bf, acc);
            }
            wmma::store_matrix_sync(Ss + rb * 16 * 128 + nf * 16, acc, 128, wmma::mem_row_major);
        }
        __syncthreads();
        for (int it = tid; it < FA_KC * 16; it += 256) {
            int r = it >> 4, c = it & 15;
            *(int4*)(KVs + r * 136 + c * 8) =
                *(const int4*)(V + (long long)(kb * FA_KC + r) * HID + colh + c * 8);
        }
        for (int rr = 0; rr < 8; rr++) {
            int r = warp * 8 + rr;
            int grow = q0 + r;
            float s0 = Ss[r * 128 + lane];
            float s1 = Ss[r * 128 + lane + 32];
            float s2 = Ss[r * 128 + lane + 64];
            float s3 = Ss[r * 128 + lane + 96];
            int gc = kb * FA_KC + lane;
            if (gc      > grow) s0 = -1e30f;
            if (gc + 32 > grow) s1 = -1e30f;
            if (gc + 64 > grow) s2 = -1e30f;
            if (gc + 96 > grow) s3 = -1e30f;
            float mx = fmaxf(fmaxf(s0, s1), fmaxf(s2, s3));
#pragma unroll
            for (int o = 16; o > 0; o >>= 1) mx = fmaxf(mx, __shfl_xor_sync(0xffffffffu, mx, o));
            float mold = mrow[r];
            float mnew = fmaxf(mold, mx);
            float alpha = __expf(mold - mnew);
            float e0 = __expf(s0 - mnew), e1 = __expf(s1 - mnew);
            float e2 = __expf(s2 - mnew), e3 = __expf(s3 - mnew);
            float sum = e0 + e1 + e2 + e3;
#pragma unroll
            for (int o = 16; o > 0; o >>= 1) sum += __shfl_xor_sync(0xffffffffu, sum, o);
            if (lane == 0) { mrow[r] = mnew; lrow[r] = lrow[r] * alpha + sum; }
            Ps[r * 136 + lane]      = __float2half(e0);
            Ps[r * 136 + lane + 32] = __float2half(e1);
            Ps[r * 136 + lane + 64] = __float2half(e2);
            Ps[r * 136 + lane + 96] = __float2half(e3);
            Os[r * 128 + lane]      *= alpha;
            Os[r * 128 + lane + 32] *= alpha;
            Os[r * 128 + lane + 64] *= alpha;
            Os[r * 128 + lane + 96] *= alpha;
        }
        __syncthreads();
        for (int nf = 0; nf < 4; nf++) {
            int ncol = ch * 64 + nf * 16;
            wmma::fragment<wmma::accumulator, 16, 16, 16, float> acc;
            wmma::load_matrix_sync(acc, Os + rb * 16 * 128 + ncol, 128, wmma::mem_row_major);
#pragma unroll
            for (int ks = 0; ks < 8; ks++) {
                wmma::fragment<wmma::matrix_a, 16, 16, 16, __half, wmma::row_major> af;
                wmma::fragment<wmma::matrix_b, 16, 16, 16, __half, wmma::row_major> bf;
                wmma::load_matrix_sync(af, Ps + rb * 16 * 136 + ks * 16, 136);
                wmma::load_matrix_sync(bf, KVs + ks * 16 * 136 + ncol, 136);
                wmma::mma_sync(acc, af, bf, acc);
            }
            wmma::store_matrix_sync(Os + rb * 16 * 128 + ncol, acc, 128, wmma::mem_row_major);
        }
        __syncthreads();
    }

    for (int rr = 0; rr < 8; rr++) {
        int r = warp * 8 + rr;
        float inv = 1.f / lrow[r];
        __half* orow = O + (long long)(q0 + r) * HID + colh;
        orow[lane]      = __float2half(Os[r * 128 + lane] * inv);
        orow[lane + 32] = __float2half(Os[r * 128 + lane + 32] * inv);
        orow[lane + 64] = __float2half(Os[r * 128 + lane + 64] * inv);
        orow[lane + 96] = __float2half(Os[r * 128 + lane + 96] * inv);
    }
}

// ---------------- cp.async multistage wmma GEMM ----------------
// CTA 128x256, 8 warps (2x4), warp tile 64x64, BK=64, 3 stages, 1 CTA/SM.
// C[M,N] = A[M,K] * B[N,K]^T, fp16 in, fp32 accum.
// OUT: 0 = float, 1 = float + residual, 2 = half.
#define GBM 128
#define GBN 256
#define GBK 64
#define GROWL 72                           // halves per smem row (64 + 8 pad), 144B
#define GA_BYTES (GBM * GROWL * 2)         // 18432
#define GB_BYTES (GBN * GROWL * 2)         // 36864
#define GSTAGE_BYTES (GA_BYTES + GB_BYTES) // 55296
#define GSTAGES 3
#define GEMM_SMEM (GSTAGES * GSTAGE_BYTES) // 165888

__device__ __forceinline__ uint32_t smem_u32(const void* p) {
    uint32_t a;
    asm("{ .reg .u64 t; cvta.to.shared.u64 t, %1; cvt.u32.u64 %0, t; }" : "=r"(a) : "l"(p));
    return a;
}
__device__ __forceinline__ void cpa16(uint32_t s, const void* g) {
    asm volatile("cp.async.cg.shared.global [%0], [%1], 16;" :: "r"(s), "l"(g));
}

template <int OUT>
__global__ __launch_bounds__(256, 1) void gemm_cp(
    const __half* __restrict__ A, const __half* __restrict__ B, void* __restrict__ Cv,
    const float* __restrict__ res, int M, int N, int K) {
    extern __shared__ char smem[];
    const int tid = threadIdx.x;
    const int warp = tid >> 5, lane = tid & 31;
    const int wm = warp & 1, wn = warp >> 1;          // 2 x 4 warp grid, 64x64 tiles
    const int m0 = blockIdx.y * GBM, n0 = blockIdx.x * GBN;
    const int nk = K / GBK;

    const int lr = tid >> 1;            // 0..127
    const int lc = (tid & 1) * 32;      // 0 or 32 halves (64B half-row)
    const uint32_t sbase = smem_u32(smem);

    auto load_tile = [&](int st, int kt) {
        const int k0 = kt * GBK;
        uint32_t sa = sbase + st * GSTAGE_BYTES + (lr * GROWL + lc) * 2;
        const __half* ga = A + (long long)(m0 + lr) * K + k0 + lc;
        cpa16(sa,      ga);
        cpa16(sa + 16, ga + 8);
        cpa16(sa + 32, ga + 16);
        cpa16(sa + 48, ga + 24);
#pragma unroll
        for (int p = 0; p < 2; p++) {
            int row = lr + p * 128;
            uint32_t sb = sbase + st * GSTAGE_BYTES + GA_BYTES + (row * GROWL + lc) * 2;
            const __half* gb = B + (long long)(n0 + row) * K + k0 + lc;
            cpa16(sb,      gb);
            cpa16(sb + 16, gb + 8);
            cpa16(sb + 32, gb + 16);
            cpa16(sb + 48, gb + 24);
        }
    };

#pragma unroll
    for (int s = 0; s < GSTAGES - 1; s++) {
        load_tile(s, s);
        asm volatile("cp.async.commit_group;" ::: "memory");
    }

    wmma::fragment<wmma::accumulator, 16, 16, 16, float> cf[4][4];
#pragma unroll
    for (int i = 0; i < 4; i++)
#pragma unroll
        for (int j = 0; j < 4; j++) wmma::fill_fragment(cf[i][j], 0.f);

    for (int kt = 0; kt < nk; kt++) {
        asm volatile("cp.async.wait_group %0;" :: "n"(GSTAGES - 2) : "memory");
        __syncthreads();
        // issue next tile's loads FIRST so they overlap the MMA block below
        const int nt = kt + GSTAGES - 1;
        if (nt < nk) load_tile(nt % GSTAGES, nt);
        asm volatile("cp.async.commit_group;" ::: "memory");

        const int buf = kt % GSTAGES;
        const __half* As = (const __half*)(smem + buf * GSTAGE_BYTES);
        const __half* Bs = As + GBM * GROWL;
#pragma unroll
        for (int kk = 0; kk < 4; kk++) {
            wmma::fragment<wmma::matrix_a, 16, 16, 16, __half, wmma::row_major> af[4];
#pragma unroll
            for (int i = 0; i < 4; i++)
                wmma::load_matrix_sync(af[i], As + (wm * 64 + i * 16) * GROWL + kk * 16, GROWL);
            wmma::fragment<wmma::matrix_b, 16, 16, 16, __half, wmma::col_major> bf[4];
#pragma unroll
            for (int j = 0; j < 4; j++)
                wmma::load_matrix_sync(bf[j], Bs + (wn * 64 + j * 16) * GROWL + kk * 16, GROWL);
#pragma unroll
            for (int i = 0; i < 4; i++)
#pragma unroll
                for (int j = 0; j < 4; j++) wmma::mma_sync(cf[i][j], af[i], bf[j], cf[i][j]);
        }
    }
    asm volatile("cp.async.wait_group 0;" ::: "memory");
    __syncthreads();

    // epilogue: per-warp 64x64 fp32 staging (8 x 16KB = 128KB <= 162KB)
    float* Cw = (float*)smem + warp * 64 * 64;
#pragma unroll
    for (int i = 0; i < 4; i++)
#pragma unroll
        for (int j = 0; j < 4; j++)
            wmma::store_matrix_sync(Cw + (i * 16) * 64 + j * 16, cf[i][j], 64, wmma::mem_row_major);
    __syncwarp();

    const int gm = m0 + wm * 64;
    const int gn = n0 + wn * 64;
    for (int it = lane; it < 64 * 16; it += 32) {
        int r = it >> 4, c4 = it & 15;
        float4 v = *(const float4*)(Cw + r * 64 + c4 * 4);
        long long grow = (long long)(gm + r) * N + gn + c4 * 4;
        if (OUT == 1) {
            float4 rv = *(const float4*)(res + grow);
            v.x += rv.x; v.y += rv.y; v.z += rv.z; v.w += rv.w;
        }
        if (OUT == 2) {
            __half2 h0 = __floats2half2_rn(v.x, v.y);
            __half2 h1 = __floats2half2_rn(v.z, v.w);
            uint2 o;
            o.x = *(uint32_t*)&h0; o.y = *(uint32_t*)&h1;
            *(uint2*)((__half*)Cv + grow) = o;
        } else {
            *(float4*)((float*)Cv + grow) = v;
        }
    }
}

// ---------------- host ----------------
extern "C" void kernel_launch(void* const* d_in, const int* in_sizes, int n_in,
                              void* d_out, int out_size) {
    const float* hidden = (const float*)d_in[0];
    const int*   pos    = (const int*)d_in[1];
    const float* ln1    = (const float*)d_in[2];
    const float* ln2    = (const float*)d_in[3];
    const float* wq     = (const float*)d_in[4];
    const float* wk     = (const float*)d_in[5];
    const float* wv     = (const float*)d_in[6];
    const float* wo     = (const float*)d_in[7];
    const float* wg     = (const float*)d_in[8];
    const float* wu     = (const float*)d_in[9];
    const float* wd     = (const float*)d_in[10];
    float* out = (float*)d_out;

    void *pWq, *pWk, *pWv, *pWo, *pWg, *pWu, *pWd;
    void *pXn, *pQp, *pKp, *pVh, *pQh, *pKh, *pAh, *pH1, *pXn2, *pGh, *pUh, *pMh;
    cudaGetSymbolAddress(&pWq, g_Wq);   cudaGetSymbolAddress(&pWk, g_Wk);
    cudaGetSymbolAddress(&pWv, g_Wv);   cudaGetSymbolAddress(&pWo, g_Wo);
    cudaGetSymbolAddress(&pWg, g_Wg);   cudaGetSymbolAddress(&pWu, g_Wu);
    cudaGetSymbolAddress(&pWd, g_Wd);
    cudaGetSymbolAddress(&pXn, g_Xn);   cudaGetSymbolAddress(&pQp, g_Qp);
    cudaGetSymbolAddress(&pKp, g_Kp);   cudaGetSymbolAddress(&pVh, g_Vh);
    cudaGetSymbolAddress(&pQh, g_Qh);   cudaGetSymbolAddress(&pKh, g_Kh);
    cudaGetSymbolAddress(&pAh, g_AttnH); cudaGetSymbolAddress(&pH1, g_H1);
    cudaGetSymbolAddress(&pXn2, g_Xn2); cudaGetSymbolAddress(&pGh, g_Gh);
    cudaGetSymbolAddress(&pUh, g_Uh);   cudaGetSymbolAddress(&pMh, g_Mh);

    cudaFuncSetAttribute(flash_kernel, cudaFuncAttributeMaxDynamicSharedMemorySize, FA_SMEM);
    cudaFuncSetAttribute(gemm_cp<0>, cudaFuncAttributeMaxDynamicSharedMemorySize, GEMM_SMEM);
    cudaFuncSetAttribute(gemm_cp<1>, cudaFuncAttributeMaxDynamicSharedMemorySize, GEMM_SMEM);
    cudaFuncSetAttribute(gemm_cp<2>, cudaFuncAttributeMaxDynamicSharedMemorySize, GEMM_SMEM);

    const long long nHH = (long long)HID * HID;
    const long long nIH = (long long)INTER * HID;
    const long long nSI = (long long)S_LEN * INTER;

    // 1: rmsnorm, 2-3: f2h q/k, 4-5: gemm Q/K (GEMM early for ncu capture)
    rmsnorm_kernel<<<S_LEN, 256>>>(hidden, ln1, (__half*)pXn);
    f2h_kernel<<<8192, 256>>>(wq, (__half*)pWq, nHH);
    f2h_kernel<<<8192, 256>>>(wk, (__half*)pWk, nHH);
    gemm_cp<2><<<dim3(HID / GBN, S_LEN / GBM), 256, GEMM_SMEM>>>(
        (const __half*)pXn, (const __half*)pWq, pQp, nullptr, S_LEN, HID, HID);
    gemm_cp<2><<<dim3(HID / GBN, S_LEN / GBM), 256, GEMM_SMEM>>>(
        (const __half*)pXn, (const __half*)pWk, pKp, nullptr, S_LEN, HID, HID);
    f2h_kernel<<<8192, 256>>>(wv, (__half*)pWv, nHH);
    gemm_cp<2><<<dim3(HID / GBN, S_LEN / GBM), 256, GEMM_SMEM>>>(
        (const __half*)pXn, (const __half*)pWv, pVh, nullptr, S_LEN, HID, HID);

    rope_kernel<<<(S_LEN * 2048 + 255) / 256, 256>>>(
        (const __half*)pQp, (const __half*)pKp, pos, (__half*)pQh, (__half*)pKh);
    f2h_kernel<<<8192, 256>>>(wo, (__half*)pWo, nHH);

    flash_kernel<<<dim3(S_LEN / FA_QR, NHEAD), 256, FA_SMEM>>>(
        (const __half*)pQh, (const __half*)pKh, (const __half*)pVh, (__half*)pAh);

    gemm_cp<1><<<dim3(HID / GBN, S_LEN / GBM), 256, GEMM_SMEM>>>(
        (const __half*)pAh, (const __half*)pWo, pH1, hidden, S_LEN, HID, HID);

    f2h_kernel<<<8192, 256>>>(wg, (__half*)pWg, nIH);
    f2h_kernel<<<8192, 256>>>(wu, (__half*)pWu, nIH);
    rmsnorm_kernel<<<S_LEN, 256>>>((const float*)pH1, ln2, (__half*)pXn2);
    gemm_cp<2><<<dim3(INTER / GBN, S_LEN / GBM), 256, GEMM_SMEM>>>(
        (const __half*)pXn2, (const __half*)pWg, pGh, nullptr, S_LEN, INTER, HID);
    gemm_cp<2><<<dim3(INTER / GBN, S_LEN / GBM), 256, GEMM_SMEM>>>(
        (const __half*)pXn2, (const __half*)pWu, pUh, nullptr, S_LEN, INTER, HID);
    f2h_kernel<<<8192, 256>>>(wd, (__half*)pWd, nIH);
    silu_kernel<<<4096, 256>>>((const __half*)pGh, (const __half*)pUh, (__half*)pMh, nSI);
    gemm_cp<1><<<dim3(HID / GBN, S_LEN / GBM), 256, GEMM_SMEM>>>(
        (const __half*)pMh, (const __half*)pWd, out, (const float*)pH1, S_LEN, HID, INTER);
}

// round 15
// speedup vs baseline: 1.0139x; 1.0017x over previous
#include <cuda_runtime.h>
#include <cuda_fp16.h>
#include <mma.h>
#include <math.h>
#include <cstdint>

using namespace nvcuda;

#define S_LEN 2048
#define HID   4096
#define NHEAD 32
#define INTER 11008

// ---------------- scratch buffers ----------------
__device__ __half g_Wq[HID * HID];
__device__ __half g_Wk[HID * HID];
__device__ __half g_Wv[HID * HID];
__device__ __half g_Wo[HID * HID];
__device__ __half g_Wg[INTER * HID];
__device__ __half g_Wu[INTER * HID];
__device__ __half g_Wd[HID * INTER];

__device__ __half g_Xn [S_LEN * HID];
__device__ __half g_Qp [S_LEN * HID];
__device__ __half g_Kp [S_LEN * HID];
__device__ __half g_Vh [S_LEN * HID];
__device__ __half g_Qh [S_LEN * HID];
__device__ __half g_Kh [S_LEN * HID];
__device__ __half g_AttnH[S_LEN * HID];
__device__ float  g_H1 [S_LEN * HID];
__device__ __half g_Xn2[S_LEN * HID];
__device__ __half g_Gh [S_LEN * INTER];
__device__ __half g_Uh [S_LEN * INTER];
__device__ __half g_Mh [S_LEN * INTER];

// ---------------- elementwise ----------------
__global__ void f2h_kernel(const float* __restrict__ in, __half* __restrict__ out, long long n) {
    long long i = ((long long)blockIdx.x * blockDim.x + threadIdx.x) * 4;
    long long stride = (long long)gridDim.x * blockDim.x * 4;
    for (; i < n; i += stride) {
        float4 v = *(const float4*)(in + i);
        *(__half2*)(out + i)     = __floats2half2_rn(v.x, v.y);
        *(__half2*)(out + i + 2) = __floats2half2_rn(v.z, v.w);
    }
}

__global__ void rmsnorm_kernel(const float* __restrict__ x, const float* __restrict__ w,
                               __half* __restrict__ out) {
    int row = blockIdx.x;
    const float* xr = x + (long long)row * HID;
    float ss = 0.f;
    for (int c = threadIdx.x * 4; c < HID; c += blockDim.x * 4) {
        float4 v = *(const float4*)(xr + c);
        ss += v.x * v.x + v.y * v.y + v.z * v.z + v.w * v.w;
    }
#pragma unroll
    for (int o = 16; o > 0; o >>= 1) ss += __shfl_xor_sync(0xffffffffu, ss, o);
    __shared__ float sh[8];
    __shared__ float inv_s;
    if ((threadIdx.x & 31) == 0) sh[threadIdx.x >> 5] = ss;
    __syncthreads();
    if (threadIdx.x == 0) {
        float t = 0.f;
        for (int i = 0; i < 8; i++) t += sh[i];
        inv_s = rsqrtf(t / (float)HID + 1e-5f);
    }
    __syncthreads();
    float inv = inv_s;
    __half* orow = out + (long long)row * HID;
    for (int c = threadIdx.x * 4; c < HID; c += blockDim.x * 4) {
        float4 v  = *(const float4*)(xr + c);
        float4 wv = *(const float4*)(w + c);
        *(__half2*)(orow + c)     = __floats2half2_rn(v.x * inv * wv.x, v.y * inv * wv.y);
        *(__half2*)(orow + c + 2) = __floats2half2_rn(v.z * inv * wv.z, v.w * inv * wv.w);
    }
}

__global__ void rope_kernel(const __half* __restrict__ Qp, const __half* __restrict__ Kp,
                            const int* __restrict__ pos,
                            __half* __restrict__ Qh, __half* __restrict__ Kh) {
    int t = blockIdx.x * blockDim.x + threadIdx.x;
    if (t >= S_LEN * 2048) return;
    int s = t >> 11;
    int r = t & 2047;
    int h = r >> 6;
    int j = r & 63;
    float p = (float)pos[s];
    float invf = exp2f(-(float)j * 0.20762050593046014f);  // 10000^(-j/64)
    float ang = p * invf;
    float c, sn;
    sincosf(ang, &sn, &c);
    long long base = (long long)s * HID + h * 128 + j;
    float q1 = __half2float(Qp[base]), q2 = __half2float(Qp[base + 64]);
    Qh[base]      = __float2half(q1 * c - q2 * sn);
    Qh[base + 64] = __float2half(q2 * c + q1 * sn);
    float k1 = __half2float(Kp[base]), k2 = __half2float(Kp[base + 64]);
    Kh[base]      = __float2half(k1 * c - k2 * sn);
    Kh[base + 64] = __float2half(k2 * c + k1 * sn);
}

__global__ void silu_kernel(const __half* __restrict__ g, const __half* __restrict__ u,
                            __half* __restrict__ out, long long n) {
    long long i = ((long long)blockIdx.x * blockDim.x + threadIdx.x) * 8;
    long long stride = (long long)gridDim.x * blockDim.x * 8;
    for (; i < n; i += stride) {
        int4 gv = *(const int4*)(g + i);
        int4 uv = *(const int4*)(u + i);
        int4 ov;
        const __half2* gh = (const __half2*)&gv;
        const __half2* uh = (const __half2*)&uv;
        __half2* oh = (__half2*)&ov;
#pragma unroll
        for (int q = 0; q < 4; q++) {
            float2 gf = __half22float2(gh[q]);
            float2 uf = __half22float2(uh[q]);
            float m0 = gf.x / (1.f + __expf(-gf.x)) * uf.x;
            float m1 = gf.y / (1.f + __expf(-gf.y)) * uf.y;
            oh[q] = __floats2half2_rn(m0, m1);
        }
        *(int4*)(out + i) = ov;
    }
}

// ---------------- flash attention (wmma, fused) ----------------
#define FA_QR 64
#define FA_KC 128
#define FA_SMEM 135680

__global__ __launch_bounds__(256) void flash_kernel(
    const __half* __restrict__ Q, const __half* __restrict__ K,
    const __half* __restrict__ V, __half* __restrict__ O) {
    extern __shared__ char sm[];
    __half* Qs  = (__half*)(sm);
    __half* KVs = (__half*)(sm + 17408);
    float*  Ss  = (float*)(sm + 52224);
    __half* Ps  = (__half*)(sm + 84992);
    float*  Os  = (float*)(sm + 102400);
    float*  mrow = (float*)(sm + 135168);
    float*  lrow = (float*)(sm + 135424);

    const int qb = blockIdx.x, h = blockIdx.y;
    const int tid = threadIdx.x, warp = tid >> 5, lane = tid & 31;
    const int rb = warp & 3, ch = warp >> 2;
    const int q0 = qb * FA_QR;
    const int colh = h * 128;
    const __half2 qscale = __half2half2(__float2half(0.08838834764831845f));

    if (tid < FA_QR) { mrow[tid] = -1e30f; lrow[tid] = 0.f; }
    for (int i = tid; i < FA_QR * 128 / 4; i += 256)
        ((float4*)Os)[i] = make_float4(0.f, 0.f, 0.f, 0.f);

    for (int it = tid; it < FA_QR * 16; it += 256) {
        int r = it >> 4, c = it & 15;
        int4 v = *(const int4*)(Q + (long long)(q0 + r) * HID + colh + c * 8);
        __half2* hv = (__half2*)&v;
        hv[0] = __hmul2(hv[0], qscale); hv[1] = __hmul2(hv[1], qscale);
        hv[2] = __hmul2(hv[2], qscale); hv[3] = __hmul2(hv[3], qscale);
        *(int4*)(Qs + r * 136 + c * 8) = v;
    }
    __syncthreads();

    const int kb_max = (q0 + FA_QR - 1) >> 7;
    for (int kb = 0; kb <= kb_max; kb++) {
        for (int it = tid; it < FA_KC * 16; it += 256) {
            int r = it >> 4, c = it & 15;
            *(int4*)(KVs + r * 136 + c * 8) =
                *(const int4*)(K + (long long)(kb * FA_KC + r) * HID + colh + c * 8);
        }
        __syncthreads();
        for (int nf = ch * 4; nf < ch * 4 + 4; nf++) {
            wmma::fragment<wmma::accumulator, 16, 16, 16, float> acc;
            wmma::fill_fragment(acc, 0.f);
#pragma unroll
            for (int ks = 0; ks < 8; ks++) {
                wmma::fragment<wmma::matrix_a, 16, 16, 16, __half, wmma::row_major> af;
                wmma::fragment<wmma::matrix_b, 16, 16, 16, __half, wmma::col_major> bf;
                wmma::load_matrix_sync(af, Qs + rb * 16 * 136 + ks * 16, 136);
                wmma::load_matrix_sync(bf, KVs + nf * 16 * 136 + ks * 16, 136);
                wmma::mma_sync(acc, af, bf, acc);
            }
            wmma::store_matrix_sync(Ss + rb * 16 * 128 + nf * 16, acc, 128, wmma::mem_row_major);
        }
        __syncthreads();
        for (int it = tid; it < FA_KC * 16; it += 256) {
            int r = it >> 4, c = it & 15;
            *(int4*)(KVs + r * 136 + c * 8) =
                *(const int4*)(V + (long long)(kb * FA_KC + r) * HID + colh + c * 8);
        }
        for (int rr = 0; rr < 8; rr++) {
            int r = warp * 8 + rr;
            int grow = q0 + r;
            float s0 = Ss[r * 128 + lane];
            float s1 = Ss[r * 128 + lane + 32];
            float s2 = Ss[r * 128 + lane + 64];
            float s3 = Ss[r * 128 + lane + 96];
            int gc = kb * FA_KC + lane;
            if (gc      > grow) s0 = -1e30f;
            if (gc + 32 > grow) s1 = -1e30f;
            if (gc + 64 > grow) s2 = -1e30f;
            if (gc + 96 > grow) s3 = -1e30f;
            float mx = fmaxf(fmaxf(s0, s1), fmaxf(s2, s3));
#pragma unroll
            for (int o = 16; o > 0; o >>= 1) mx = fmaxf(mx, __shfl_xor_sync(0xffffffffu, mx, o));
            float mold = mrow[r];
            float mnew = fmaxf(mold, mx);
            float alpha = __expf(mold - mnew);
            float e0 = __expf(s0 - mnew), e1 = __expf(s1 - mnew);
            float e2 = __expf(s2 - mnew), e3 = __expf(s3 - mnew);
            float sum = e0 + e1 + e2 + e3;
#pragma unroll
            for (int o = 16; o > 0; o >>= 1) sum += __shfl_xor_sync(0xffffffffu, sum, o);
            if (lane == 0) { mrow[r] = mnew; lrow[r] = lrow[r] * alpha + sum; }
            Ps[r * 136 + lane]      = __float2half(e0);
            Ps[r * 136 + lane + 32] = __float2half(e1);
            Ps[r * 136 + lane + 64] = __float2half(e2);
            Ps[r * 136 + lane + 96] = __float2half(e3);
            Os[r * 128 + lane]      *= alpha;
            Os[r * 128 + lane + 32] *= alpha;
            Os[r * 128 + lane + 64] *= alpha;
            Os[r * 128 + lane + 96] *= alpha;
        }
        __syncthreads();
        for (int nf = 0; nf < 4; nf++) {
            int ncol = ch * 64 + nf * 16;
            wmma::fragment<wmma::accumulator, 16, 16, 16, float> acc;
            wmma::load_matrix_sync(acc, Os + rb * 16 * 128 + ncol, 128, wmma::mem_row_major);
#pragma unroll
            for (int ks = 0; ks < 8; ks++) {
                wmma::fragment<wmma::matrix_a, 16, 16, 16, __half, wmma::row_major> af;
                wmma::fragment<wmma::matrix_b, 16, 16, 16, __half, wmma::row_major> bf;
                wmma::load_matrix_sync(af, Ps + rb * 16 * 136 + ks * 16, 136);
                wmma::load_matrix_sync(bf, KVs + ks * 16 * 136 + ncol, 136);
                wmma::mma_sync(acc, af, bf, acc);
            }
            wmma::store_matrix_sync(Os + rb * 16 * 128 + ncol, acc, 128, wmma::mem_row_major);
        }
        __syncthreads();
    }

    for (int rr = 0; rr < 8; rr++) {
        int r = warp * 8 + rr;
        float inv = 1.f / lrow[r];
        __half* orow = O + (long long)(q0 + r) * HID + colh;
        orow[lane]      = __float2half(Os[r * 128 + lane] * inv);
        orow[lane + 32] = __float2half(Os[r * 128 + lane + 32] * inv);
        orow[lane + 64] = __float2half(Os[r * 128 + lane + 64] * inv);
        orow[lane + 96] = __float2half(Os[r * 128 + lane + 96] * inv);
    }
}

// ---------------- raw mma.sync GEMM (R12 shell: 128x256 CTA, 8 warps, 64x64/warp) ----
// C[M,N] = A[M,K] * B[N,K]^T, fp16 in, fp32 accum.
// OUT: 0 = float, 1 = float + residual, 2 = half.
#define GBM 128
#define GBN 256
#define GBK 32
#define GROWL 40                           // halves per smem row (32 + 8 pad), 80B
#define GA_BYTES (GBM * GROWL * 2)         // 10240
#define GB_BYTES (GBN * GROWL * 2)         // 20480
#define GSTAGE_BYTES (GA_BYTES + GB_BYTES) // 30720
#define GSTAGES 3
#define GEMM_SMEM 131072                   // 3 stages (92160) vs epilogue staging 128KB

__device__ __forceinline__ uint32_t smem_u32(const void* p) {
    uint32_t a;
    asm("{ .reg .u64 t; cvta.to.shared.u64 t, %1; cvt.u32.u64 %0, t; }" : "=r"(a) : "l"(p));
    return a;
}
__device__ __forceinline__ void cpa16(uint32_t s, const void* g) {
    asm volatile("cp.async.cg.shared.global [%0], [%1], 16;" :: "r"(s), "l"(g));
}
#define LDM4(r, addr) \
    asm volatile("ldmatrix.sync.aligned.m8n8.x4.shared.b16 {%0,%1,%2,%3}, [%4];" \
                 : "=r"((r)[0]), "=r"((r)[1]), "=r"((r)[2]), "=r"((r)[3]) : "r"(addr))
#define MMA16816(c, a, b0, b1) \
    asm volatile("mma.sync.aligned.m16n8k16.row.col.f32.f16.f16.f32 " \
                 "{%0,%1,%2,%3},{%4,%5,%6,%7},{%8,%9},{%0,%1,%2,%3};" \
                 : "+f"((c)[0]), "+f"((c)[1]), "+f"((c)[2]), "+f"((c)[3]) \
                 : "r"((a)[0]), "r"((a)[1]), "r"((a)[2]), "r"((a)[3]), "r"(b0), "r"(b1))

template <int OUT>
__global__ __launch_bounds__(256, 1) void gemm_cp(
    const __half* __restrict__ A, const __half* __restrict__ B, void* __restrict__ Cv,
    const float* __restrict__ res, int M, int N, int K) {
    extern __shared__ char smem[];
    const int tid = threadIdx.x;
    const int warp = tid >> 5, lane = tid & 31;
    const int wm = warp & 1, wn = warp >> 1;          // 2 x 4 warp grid, 64x64 tiles
    const int m0 = blockIdx.y * GBM, n0 = blockIdx.x * GBN;
    const int nk = K / GBK;

    const int lr = tid >> 1;            // 0..127
    const int lc = (tid & 1) * 16;      // 0 or 16 halves
    const uint32_t sbase = smem_u32(smem);

    auto load_tile = [&](int st, int kt) {
        const int k0 = kt * GBK;
        uint32_t sa = sbase + st * GSTAGE_BYTES + (lr * GROWL + lc) * 2;
        const __half* ga = A + (long long)(m0 + lr) * K + k0 + lc;
        cpa16(sa, ga);
        cpa16(sa + 16, ga + 8);
#pragma unroll
        for (int p = 0; p < 2; p++) {
            int row = lr + p * 128;
            uint32_t sb = sbase + st * GSTAGE_BYTES + GA_BYTES + (row * GROWL + lc) * 2;
            const __half* gb = B + (long long)(n0 + row) * K + k0 + lc;
            cpa16(sb, gb);
            cpa16(sb + 16, gb + 8);
        }
    };

#pragma unroll
    for (int s = 0; s < GSTAGES - 1; s++) {
        load_tile(s, s);
        asm volatile("cp.async.commit_group;" ::: "memory");
    }

    float cacc[4][8][4];
#pragma unroll
    for (int i = 0; i < 4; i++)
#pragma unroll
        for (int j = 0; j < 8; j++)
#pragma unroll
            for (int e = 0; e < 4; e++) cacc[i][j][e] = 0.f;

    // per-lane ldmatrix offsets (in halves, within the tile): row = l&15, chunk = l>>4
    const int lrow = lane & 15;
    const int lchunk = (lane >> 4) * 8;
    const uint32_t aoff = ((uint32_t)(wm * 64 + lrow) * GROWL + lchunk) * 2;
    const uint32_t boff = ((uint32_t)(wn * 64 + lrow) * GROWL + lchunk) * 2;

    uint32_t fa[2][4][4], fb[2][4][4];

    for (int kt = 0; kt < nk; kt++) {
        asm volatile("cp.async.wait_group %0;" :: "n"(GSTAGES - 2) : "memory");
        __syncthreads();
        const int buf = kt % GSTAGES;
        const uint32_t aBase = sbase + buf * GSTAGE_BYTES + aoff;
        const uint32_t bBase = sbase + buf * GSTAGE_BYTES + GA_BYTES + boff;

        // load k-slice 0 fragments
#pragma unroll
        for (int i = 0; i < 4; i++) LDM4(fa[0][i], aBase + (uint32_t)(i * 16 * GROWL * 2));
#pragma unroll
        for (int g = 0; g < 4; g++) LDM4(fb[0][g], bBase + (uint32_t)(g * 16 * GROWL * 2));

#pragma unroll
        for (int kk = 0; kk < 2; kk++) {
            if (kk == 0) {  // prefetch slice 1 while computing slice 0
#pragma unroll
                for (int i = 0; i < 4; i++) LDM4(fa[1][i], aBase + 32 + (uint32_t)(i * 16 * GROWL * 2));
#pragma unroll
                for (int g = 0; g < 4; g++) LDM4(fb[1][g], bBase + 32 + (uint32_t)(g * 16 * GROWL * 2));
            }
#pragma unroll
            for (int i = 0; i < 4; i++)
#pragma unroll
                for (int j = 0; j < 8; j++) {
                    const uint32_t* bb = fb[kk][j >> 1];
                    const int odd = j & 1;
                    MMA16816(cacc[i][j], fa[kk][i], bb[odd], bb[odd + 2]);
                }
        }

        const int nt = kt + GSTAGES - 1;
        if (nt < nk) load_tile(nt % GSTAGES, nt);
        asm volatile("cp.async.commit_group;" ::: "memory");
    }
    asm volatile("cp.async.wait_group 0;" ::: "memory");
    __syncthreads();

    // epilogue: per-warp 64x64 fp32 staging (8 x 16KB = 128KB)
    float* Cw = (float*)smem + warp * 64 * 64;
    const int erow = lane >> 2;
    const int ecol = (lane & 3) * 2;
#pragma unroll
    for (int i = 0; i < 4; i++)
#pragma unroll
        for (int j = 0; j < 8; j++) {
            float* p0 = Cw + (i * 16 + erow) * 64 + j * 8 + ecol;
            *(float2*)p0            = make_float2(cacc[i][j][0], cacc[i][j][1]);
            *(float2*)(p0 + 8 * 64) = make_float2(cacc[i][j][2], cacc[i][j][3]);
        }
    __syncwarp();

    const int gm = m0 + wm * 64;
    const int gn = n0 + wn * 64;
    for (int it = lane; it < 64 * 16; it += 32) {
        int r = it >> 4, c4 = it & 15;
        float4 v = *(const float4*)(Cw + r * 64 + c4 * 4);
        long long grow = (long long)(gm + r) * N + gn + c4 * 4;
        if (OUT == 1) {
            float4 rv = *(const float4*)(res + grow);
            v.x += rv.x; v.y += rv.y; v.z += rv.z; v.w += rv.w;
        }
        if (OUT == 2) {
            __half2 h0 = __floats2half2_rn(v.x, v.y);
            __half2 h1 = __floats2half2_rn(v.z, v.w);
            uint2 o;
            o.x = *(uint32_t*)&h0; o.y = *(uint32_t*)&h1;
            *(uint2*)((__half*)Cv + grow) = o;
        } else {
            *(float4*)((float*)Cv + grow) = v;
        }
    }
}

// ---------------- host ----------------
extern "C" void kernel_launch(void* const* d_in, const int* in_sizes, int n_in,
                              void* d_out, int out_size) {
    const float* hidden = (const float*)d_in[0];
    const int*   pos    = (const int*)d_in[1];
    const float* ln1    = (const float*)d_in[2];
    const float* ln2    = (const float*)d_in[3];
    const float* wq     = (const float*)d_in[4];
    const float* wk     = (const float*)d_in[5];
    const float* wv     = (const float*)d_in[6];
    const float* wo     = (const float*)d_in[7];
    const float* wg     = (const float*)d_in[8];
    const float* wu     = (const float*)d_in[9];
    const float* wd     = (const float*)d_in[10];
    float* out = (float*)d_out;

    void *pWq, *pWk, *pWv, *pWo, *pWg, *pWu, *pWd;
    void *pXn, *pQp, *pKp, *pVh, *pQh, *pKh, *pAh, *pH1, *pXn2, *pGh, *pUh, *pMh;
    cudaGetSymbolAddress(&pWq, g_Wq);   cudaGetSymbolAddress(&pWk, g_Wk);
    cudaGetSymbolAddress(&pWv, g_Wv);   cudaGetSymbolAddress(&pWo, g_Wo);
    cudaGetSymbolAddress(&pWg, g_Wg);   cudaGetSymbolAddress(&pWu, g_Wu);
    cudaGetSymbolAddress(&pWd, g_Wd);
    cudaGetSymbolAddress(&pXn, g_Xn);   cudaGetSymbolAddress(&pQp, g_Qp);
    cudaGetSymbolAddress(&pKp, g_Kp);   cudaGetSymbolAddress(&pVh, g_Vh);
    cudaGetSymbolAddress(&pQh, g_Qh);   cudaGetSymbolAddress(&pKh, g_Kh);
    cudaGetSymbolAddress(&pAh, g_AttnH); cudaGetSymbolAddress(&pH1, g_H1);
    cudaGetSymbolAddress(&pXn2, g_Xn2); cudaGetSymbolAddress(&pGh, g_Gh);
    cudaGetSymbolAddress(&pUh, g_Uh);   cudaGetSymbolAddress(&pMh, g_Mh);

    cudaFuncSetAttribute(flash_kernel, cudaFuncAttributeMaxDynamicSharedMemorySize, FA_SMEM);
    cudaFuncSetAttribute(gemm_cp<0>, cudaFuncAttributeMaxDynamicSharedMemorySize, GEMM_SMEM);
    cudaFuncSetAttribute(gemm_cp<1>, cudaFuncAttributeMaxDynamicSharedMemorySize, GEMM_SMEM);
    cudaFuncSetAttribute(gemm_cp<2>, cudaFuncAttributeMaxDynamicSharedMemorySize, GEMM_SMEM);

    const long long nHH = (long long)HID * HID;
    const long long nIH = (long long)INTER * HID;
    const long long nSI = (long long)S_LEN * INTER;

    // 1: rmsnorm, 2-3: f2h q/k, 4: gemm Q (early for ncu capture)
    rmsnorm_kernel<<<S_LEN, 256>>>(hidden, ln1, (__half*)pXn);
    f2h_kernel<<<8192, 256>>>(wq, (__half*)pWq, nHH);
    f2h_kernel<<<8192, 256>>>(wk, (__half*)pWk, nHH);
    gemm_cp<2><<<dim3(HID / GBN, S_LEN / GBM), 256, GEMM_SMEM>>>(
        (const __half*)pXn, (const __half*)pWq, pQp, nullptr, S_LEN, HID, HID);
    gemm_cp<2><<<dim3(HID / GBN, S_LEN / GBM), 256, GEMM_SMEM>>>(
        (const __half*)pXn, (const __half*)pWk, pKp, nullptr, S_LEN, HID, HID);
    f2h_kernel<<<8192, 256>>>(wv, (__half*)pWv, nHH);
    gemm_cp<2><<<dim3(HID / GBN, S_LEN / GBM), 256, GEMM_SMEM>>>(
        (const __half*)pXn, (const __half*)pWv, pVh, nullptr, S_LEN, HID, HID);

    rope_kernel<<<(S_LEN * 2048 + 255) / 256, 256>>>(
        (const __half*)pQp, (const __half*)pKp, pos, (__half*)pQh, (__half*)pKh);
    f2h_kernel<<<8192, 256>>>(wo, (__half*)pWo, nHH);

    flash_kernel<<<dim3(S_LEN / FA_QR, NHEAD), 256, FA_SMEM>>>(
        (const __half*)pQh, (const __half*)pKh, (const __half*)pVh, (__half*)pAh);

    gemm_cp<1><<<dim3(HID / GBN, S_LEN / GBM), 256, GEMM_SMEM>>>(
        (const __half*)pAh, (const __half*)pWo, pH1, hidden, S_LEN, HID, HID);

    f2h_kernel<<<8192, 256>>>(wg, (__half*)pWg, nIH);
    f2h_kernel<<<8192, 256>>>(wu, (__half*)pWu, nIH);
    rmsnorm_kernel<<<S_LEN, 256>>>((const float*)pH1, ln2, (__half*)pXn2);
    gemm_cp<2><<<dim3(INTER / GBN, S_LEN / GBM), 256, GEMM_SMEM>>>(
        (const __half*)pXn2, (const __half*)pWg, pGh, nullptr, S_LEN, INTER, HID);
    gemm_cp<2><<<dim3(INTER / GBN, S_LEN / GBM), 256, GEMM_SMEM>>>(
        (const __half*)pXn2, (const __half*)pWu, pUh, nullptr, S_LEN, INTER, HID);
    f2h_kernel<<<8192, 256>>>(wd, (__half*)pWd, nIH);
    silu_kernel<<<4096, 256>>>((const __half*)pGh, (const __half*)pUh, (__half*)pMh, nSI);
    gemm_cp<1><<<dim3(HID / GBN, S_LEN / GBM), 256, GEMM_SMEM>>>(
        (const __half*)pMh, (const __half*)pWd, out, (const float*)pH1, S_LEN, HID, INTER);
}

// round 16
// speedup vs baseline: 1.2523x; 1.2351x over previous
#include <cuda_runtime.h>
#include <cuda_fp16.h>
#include <mma.h>
#include <math.h>
#include <cstdint>

using namespace nvcuda;

#define S_LEN 2048
#define HID   4096
#define NHEAD 32
#define INTER 11008

// ---------------- scratch buffers ----------------
__device__ __half g_Wq[HID * HID];
__device__ __half g_Wk[HID * HID];
__device__ __half g_Wv[HID * HID];
__device__ __half g_Wo[HID * HID];
__device__ __half g_Wg[INTER * HID];
__device__ __half g_Wu[INTER * HID];
__device__ __half g_Wd[HID * INTER];

__device__ __half g_Xn [S_LEN * HID];
__device__ __half g_Qp [S_LEN * HID];
__device__ __half g_Kp [S_LEN * HID];
__device__ __half g_Vh [S_LEN * HID];
__device__ __half g_Qh [S_LEN * HID];
__device__ __half g_Kh [S_LEN * HID];
__device__ __half g_AttnH[S_LEN * HID];
__device__ float  g_H1 [S_LEN * HID];
__device__ __half g_Xn2[S_LEN * HID];
__device__ __half g_Gh [S_LEN * INTER];
__device__ __half g_Uh [S_LEN * INTER];
__device__ __half g_Mh [S_LEN * INTER];

// ---------------- elementwise ----------------
__global__ void f2h_kernel(const float* __restrict__ in, __half* __restrict__ out, long long n) {
    long long i = ((long long)blockIdx.x * blockDim.x + threadIdx.x) * 4;
    long long stride = (long long)gridDim.x * blockDim.x * 4;
    for (; i < n; i += stride) {
        float4 v = *(const float4*)(in + i);
        *(__half2*)(out + i)     = __floats2half2_rn(v.x, v.y);
        *(__half2*)(out + i + 2) = __floats2half2_rn(v.z, v.w);
    }
}

__global__ void rmsnorm_kernel(const float* __restrict__ x, const float* __restrict__ w,
                               __half* __restrict__ out) {
    int row = blockIdx.x;
    const float* xr = x + (long long)row * HID;
    float ss = 0.f;
    for (int c = threadIdx.x * 4; c < HID; c += blockDim.x * 4) {
        float4 v = *(const float4*)(xr + c);
        ss += v.x * v.x + v.y * v.y + v.z * v.z + v.w * v.w;
    }
#pragma unroll
    for (int o = 16; o > 0; o >>= 1) ss += __shfl_xor_sync(0xffffffffu, ss, o);
    __shared__ float sh[8];
    __shared__ float inv_s;
    if ((threadIdx.x & 31) == 0) sh[threadIdx.x >> 5] = ss;
    __syncthreads();
    if (threadIdx.x == 0) {
        float t = 0.f;
        for (int i = 0; i < 8; i++) t += sh[i];
        inv_s = rsqrtf(t / (float)HID + 1e-5f);
    }
    __syncthreads();
    float inv = inv_s;
    __half* orow = out + (long long)row * HID;
    for (int c = threadIdx.x * 4; c < HID; c += blockDim.x * 4) {
        float4 v  = *(const float4*)(xr + c);
        float4 wv = *(const float4*)(w + c);
        *(__half2*)(orow + c)     = __floats2half2_rn(v.x * inv * wv.x, v.y * inv * wv.y);
        *(__half2*)(orow + c + 2) = __floats2half2_rn(v.z * inv * wv.z, v.w * inv * wv.w);
    }
}

__global__ void rope_kernel(const __half* __restrict__ Qp, const __half* __restrict__ Kp,
                            const int* __restrict__ pos,
                            __half* __restrict__ Qh, __half* __restrict__ Kh) {
    int t = blockIdx.x * blockDim.x + threadIdx.x;
    if (t >= S_LEN * 2048) return;
    int s = t >> 11;
    int r = t & 2047;
    int h = r >> 6;
    int j = r & 63;
    float p = (float)pos[s];
    float invf = exp2f(-(float)j * 0.20762050593046014f);  // 10000^(-j/64)
    float ang = p * invf;
    float c, sn;
    sincosf(ang, &sn, &c);
    long long base = (long long)s * HID + h * 128 + j;
    float q1 = __half2float(Qp[base]), q2 = __half2float(Qp[base + 64]);
    Qh[base]      = __float2half(q1 * c - q2 * sn);
    Qh[base + 64] = __float2half(q2 * c + q1 * sn);
    float k1 = __half2float(Kp[base]), k2 = __half2float(Kp[base + 64]);
    Kh[base]      = __float2half(k1 * c - k2 * sn);
    Kh[base + 64] = __float2half(k2 * c + k1 * sn);
}

__global__ void silu_kernel(const __half* __restrict__ g, const __half* __restrict__ u,
                            __half* __restrict__ out, long long n) {
    long long i = ((long long)blockIdx.x * blockDim.x + threadIdx.x) * 8;
    long long stride = (long long)gridDim.x * blockDim.x * 8;
    for (; i < n; i += stride) {
        int4 gv = *(const int4*)(g + i);
        int4 uv = *(const int4*)(u + i);
        int4 ov;
        const __half2* gh = (const __half2*)&gv;
        const __half2* uh = (const __half2*)&uv;
        __half2* oh = (__half2*)&ov;
#pragma unroll
        for (int q = 0; q < 4; q++) {
            float2 gf = __half22float2(gh[q]);
            float2 uf = __half22float2(uh[q]);
            float m0 = gf.x / (1.f + __expf(-gf.x)) * uf.x;
            float m1 = gf.y / (1.f + __expf(-gf.y)) * uf.y;
            oh[q] = __floats2half2_rn(m0, m1);
        }
        *(int4*)(out + i) = ov;
    }
}

// ---------------- flash attention (wmma, fused) ----------------
#define FA_QR 64
#define FA_KC 128
#define FA_SMEM 135680

__global__ __launch_bounds__(256) void flash_kernel(
    const __half* __restrict__ Q, const __half* __restrict__ K,
    const __half* __restrict__ V, __half* __restrict__ O) {
    extern __shared__ char sm[];
    __half* Qs  = (__half*)(sm);
    __half* KVs = (__half*)(sm + 17408);
    float*  Ss  = (float*)(sm + 52224);
    __half* Ps  = (__half*)(sm + 84992);
    float*  Os  = (float*)(sm + 102400);
    float*  mrow = (float*)(sm + 135168);
    float*  lrow = (float*)(sm + 135424);

    const int qb = blockIdx.x, h = blockIdx.y;
    const int tid = threadIdx.x, warp = tid >> 5, lane = tid & 31;
    const int rb = warp & 3, ch = warp >> 2;
    const int q0 = qb * FA_QR;
    const int colh = h * 128;
    const __half2 qscale = __half2half2(__float2half(0.08838834764831845f));

    if (tid < FA_QR) { mrow[tid] = -1e30f; lrow[tid] = 0.f; }
    for (int i = tid; i < FA_QR * 128 / 4; i += 256)
        ((float4*)Os)[i] = make_float4(0.f, 0.f, 0.f, 0.f);

    for (int it = tid; it < FA_QR * 16; it += 256) {
        int r = it >> 4, c = it & 15;
        int4 v = *(const int4*)(Q + (long long)(q0 + r) * HID + colh + c * 8);
        __half2* hv = (__half2*)&v;
        hv[0] = __hmul2(hv[0], qscale); hv[1] = __hmul2(hv[1], qscale);
        hv[2] = __hmul2(hv[2], qscale); hv[3] = __hmul2(hv[3], qscale);
        *(int4*)(Qs + r * 136 + c * 8) = v;
    }
    __syncthreads();

    const int kb_max = (q0 + FA_QR - 1) >> 7;
    for (int kb = 0; kb <= kb_max; kb++) {
        for (int it = tid; it < FA_KC * 16; it += 256) {
            int r = it >> 4, c = it & 15;
            *(int4*)(KVs + r * 136 + c * 8) =
                *(const int4*)(K + (long long)(kb * FA_KC + r) * HID + colh + c * 8);
        }
        __syncthreads();
        for (int nf = ch * 4; nf < ch * 4 + 4; nf++) {
            wmma::fragment<wmma::accumulator, 16, 16, 16, float> acc;
            wmma::fill_fragment(acc, 0.f);
#pragma unroll
            for (int ks = 0; ks < 8; ks++) {
                wmma::fragment<wmma::matrix_a, 16, 16, 16, __half, wmma::row_major> af;
                wmma::fragment<wmma::matrix_b, 16, 16, 16, __half, wmma::col_major> bf;
                wmma::load_matrix_sync(af, Qs + rb * 16 * 136 + ks * 16, 136);
                wmma::load_matrix_sync(bf, KVs + nf * 16 * 136 + ks * 16, 136);
                wmma::mma_sync(acc, af, bf, acc);
            }
            wmma::store_matrix_sync(Ss + rb * 16 * 128 + nf * 16, acc, 128, wmma::mem_row_major);
        }
        __syncthreads();
        for (int it = tid; it < FA_KC * 16; it += 256) {
            int r = it >> 4, c = it & 15;
            *(int4*)(KVs + r * 136 + c * 8) =
                *(const int4*)(V + (long long)(kb * FA_KC + r) * HID + colh + c * 8);
        }
        for (int rr = 0; rr < 8; rr++) {
            int r = warp * 8 + rr;
            int grow = q0 + r;
            float s0 = Ss[r * 128 + lane];
            float s1 = Ss[r * 128 + lane + 32];
            float s2 = Ss[r * 128 + lane + 64];
            float s3 = Ss[r * 128 + lane + 96];
            int gc = kb * FA_KC + lane;
            if (gc      > grow) s0 = -1e30f;
            if (gc + 32 > grow) s1 = -1e30f;
            if (gc + 64 > grow) s2 = -1e30f;
            if (gc + 96 > grow) s3 = -1e30f;
            float mx = fmaxf(fmaxf(s0, s1), fmaxf(s2, s3));
#pragma unroll
            for (int o = 16; o > 0; o >>= 1) mx = fmaxf(mx, __shfl_xor_sync(0xffffffffu, mx, o));
            float mold = mrow[r];
            float mnew = fmaxf(mold, mx);
            float alpha = __expf(mold - mnew);
            float e0 = __expf(s0 - mnew), e1 = __expf(s1 - mnew);
            float e2 = __expf(s2 - mnew), e3 = __expf(s3 - mnew);
            float sum = e0 + e1 + e2 + e3;
#pragma unroll
            for (int o = 16; o > 0; o >>= 1) sum += __shfl_xor_sync(0xffffffffu, sum, o);
            if (lane == 0) { mrow[r] = mnew; lrow[r] = lrow[r] * alpha + sum; }
            Ps[r * 136 + lane]      = __float2half(e0);
            Ps[r * 136 + lane + 32] = __float2half(e1);
            Ps[r * 136 + lane + 64] = __float2half(e2);
            Ps[r * 136 + lane + 96] = __float2half(e3);
            Os[r * 128 + lane]      *= alpha;
            Os[r * 128 + lane + 32] *= alpha;
            Os[r * 128 + lane + 64] *= alpha;
            Os[r * 128 + lane + 96] *= alpha;
        }
        __syncthreads();
        for (int nf = 0; nf < 4; nf++) {
            int ncol = ch * 64 + nf * 16;
            wmma::fragment<wmma::accumulator, 16, 16, 16, float> acc;
            wmma::load_matrix_sync(acc, Os + rb * 16 * 128 + ncol, 128, wmma::mem_row_major);
#pragma unroll
            for (int ks = 0; ks < 8; ks++) {
                wmma::fragment<wmma::matrix_a, 16, 16, 16, __half, wmma::row_major> af;
                wmma::fragment<wmma::matrix_b, 16, 16, 16, __half, wmma::row_major> bf;
                wmma::load_matrix_sync(af, Ps + rb * 16 * 136 + ks * 16, 136);
                wmma::load_matrix_sync(bf, KVs + ks * 16 * 136 + ncol, 136);
                wmma::mma_sync(acc, af, bf, acc);
            }
            wmma::store_matrix_sync(Os + rb * 16 * 128 + ncol, acc, 128, wmma::mem_row_major);
        }
        __syncthreads();
    }

    for (int rr = 0; rr < 8; rr++) {
        int r = warp * 8 + rr;
        float inv = 1.f / lrow[r];
        __half* orow = O + (long long)(q0 + r) * HID + colh;
        orow[lane]      = __float2half(Os[r * 128 + lane] * inv);
        orow[lane + 32] = __float2half(Os[r * 128 + lane + 32] * inv);
        orow[lane + 64] = __float2half(Os[r * 128 + lane + 64] * inv);
        orow[lane + 96] = __float2half(Os[r * 128 + lane + 96] * inv);
    }
}

// ---------------- cp.async multistage wmma GEMM (R12 config, 4 stages) ----------------
// CTA 128x256, 8 warps (2x4), warp tile 64x64, BK=32, deferred loads, 1 CTA/SM.
// C[M,N] = A[M,K] * B[N,K]^T, fp16 in, fp32 accum.
// OUT: 0 = float, 1 = float + residual, 2 = half.
#define GBM 128
#define GBN 256
#define GBK 32
#define GROWL 40                           // halves per smem row (32 + 8 pad)
#define GA_BYTES (GBM * GROWL * 2)         // 10240
#define GB_BYTES (GBN * GROWL * 2)         // 20480
#define GSTAGE_BYTES (GA_BYTES + GB_BYTES) // 30720
#define GSTAGES 4
#define GEMM_SMEM 131072                   // 4 stages (122880) vs epilogue staging 128KB

__device__ __forceinline__ uint32_t smem_u32(const void* p) {
    uint32_t a;
    asm("{ .reg .u64 t; cvta.to.shared.u64 t, %1; cvt.u32.u64 %0, t; }" : "=r"(a) : "l"(p));
    return a;
}
__device__ __forceinline__ void cpa16(uint32_t s, const void* g) {
    asm volatile("cp.async.cg.shared.global [%0], [%1], 16;" :: "r"(s), "l"(g));
}

template <int OUT>
__global__ __launch_bounds__(256, 1) void gemm_cp(
    const __half* __restrict__ A, const __half* __restrict__ B, void* __restrict__ Cv,
    const float* __restrict__ res, int M, int N, int K) {
    extern __shared__ char smem[];
    const int tid = threadIdx.x;
    const int warp = tid >> 5, lane = tid & 31;
    const int wm = warp & 1, wn = warp >> 1;          // 2 x 4 warp grid, 64x64 tiles
    const int m0 = blockIdx.y * GBM, n0 = blockIdx.x * GBN;
    const int nk = K / GBK;

    const int lr = tid >> 1;            // 0..127
    const int lc = (tid & 1) * 16;      // 0 or 16 halves
    const uint32_t sbase = smem_u32(smem);

    auto load_tile = [&](int st, int kt) {
        const int k0 = kt * GBK;
        uint32_t sa = sbase + st * GSTAGE_BYTES + (lr * GROWL + lc) * 2;
        const __half* ga = A + (long long)(m0 + lr) * K + k0 + lc;
        cpa16(sa, ga);
        cpa16(sa + 16, ga + 8);
#pragma unroll
        for (int p = 0; p < 2; p++) {
            int row = lr + p * 128;
            uint32_t sb = sbase + st * GSTAGE_BYTES + GA_BYTES + (row * GROWL + lc) * 2;
            const __half* gb = B + (long long)(n0 + row) * K + k0 + lc;
            cpa16(sb, gb);
            cpa16(sb + 16, gb + 8);
        }
    };

#pragma unroll
    for (int s = 0; s < GSTAGES - 1; s++) {
        load_tile(s, s);
        asm volatile("cp.async.commit_group;" ::: "memory");
    }

    wmma::fragment<wmma::accumulator, 16, 16, 16, float> cf[4][4];
#pragma unroll
    for (int i = 0; i < 4; i++)
#pragma unroll
        for (int j = 0; j < 4; j++) wmma::fill_fragment(cf[i][j], 0.f);

    for (int kt = 0; kt < nk; kt++) {
        asm volatile("cp.async.wait_group %0;" :: "n"(GSTAGES - 2) : "memory");
        __syncthreads();
        const int buf = kt % GSTAGES;
        const __half* As = (const __half*)(smem + buf * GSTAGE_BYTES);
        const __half* Bs = As + GBM * GROWL;
#pragma unroll
        for (int kk = 0; kk < 2; kk++) {
            wmma::fragment<wmma::matrix_a, 16, 16, 16, __half, wmma::row_major> af[4];
#pragma unroll
            for (int i = 0; i < 4; i++)
                wmma::load_matrix_sync(af[i], As + (wm * 64 + i * 16) * GROWL + kk * 16, GROWL);
            wmma::fragment<wmma::matrix_b, 16, 16, 16, __half, wmma::col_major> bf[4];
#pragma unroll
            for (int j = 0; j < 4; j++)
                wmma::load_matrix_sync(bf[j], Bs + (wn * 64 + j * 16) * GROWL + kk * 16, GROWL);
#pragma unroll
            for (int i = 0; i < 4; i++)
#pragma unroll
                for (int j = 0; j < 4; j++) wmma::mma_sync(cf[i][j], af[i], bf[j], cf[i][j]);
        }
        const int nt = kt + GSTAGES - 1;
        if (nt < nk) load_tile(nt % GSTAGES, nt);
        asm volatile("cp.async.commit_group;" ::: "memory");
    }
    asm volatile("cp.async.wait_group 0;" ::: "memory");
    __syncthreads();

    // epilogue: per-warp 64x64 fp32 staging (8 x 16KB = 128KB)
    float* Cw = (float*)smem + warp * 64 * 64;
#pragma unroll
    for (int i = 0; i < 4; i++)
#pragma unroll
        for (int j = 0; j < 4; j++)
            wmma::store_matrix_sync(Cw + (i * 16) * 64 + j * 16, cf[i][j], 64, wmma::mem_row_major);
    __syncwarp();

    const int gm = m0 + wm * 64;
    const int gn = n0 + wn * 64;
    for (int it = lane; it < 64 * 16; it += 32) {
        int r = it >> 4, c4 = it & 15;
        float4 v = *(const float4*)(Cw + r * 64 + c4 * 4);
        long long grow = (long long)(gm + r) * N + gn + c4 * 4;
        if (OUT == 1) {
            float4 rv = *(const float4*)(res + grow);
            v.x += rv.x; v.y += rv.y; v.z += rv.z; v.w += rv.w;
        }
        if (OUT == 2) {
            __half2 h0 = __floats2half2_rn(v.x, v.y);
            __half2 h1 = __floats2half2_rn(v.z, v.w);
            uint2 o;
            o.x = *(uint32_t*)&h0; o.y = *(uint32_t*)&h1;
            *(uint2*)((__half*)Cv + grow) = o;
        } else {
            *(float4*)((float*)Cv + grow) = v;
        }
    }
}

// ---------------- host ----------------
extern "C" void kernel_launch(void* const* d_in, const int* in_sizes, int n_in,
                              void* d_out, int out_size) {
    const float* hidden = (const float*)d_in[0];
    const int*   pos    = (const int*)d_in[1];
    const float* ln1    = (const float*)d_in[2];
    const float* ln2    = (const float*)d_in[3];
    const float* wq     = (const float*)d_in[4];
    const float* wk     = (const float*)d_in[5];
    const float* wv     = (const float*)d_in[6];
    const float* wo     = (const float*)d_in[7];
    const float* wg     = (const float*)d_in[8];
    const float* wu     = (const float*)d_in[9];
    const float* wd     = (const float*)d_in[10];
    float* out = (float*)d_out;

    void *pWq, *pWk, *pWv, *pWo, *pWg, *pWu, *pWd;
    void *pXn, *pQp, *pKp, *pVh, *pQh, *pKh, *pAh, *pH1, *pXn2, *pGh, *pUh, *pMh;
    cudaGetSymbolAddress(&pWq, g_Wq);   cudaGetSymbolAddress(&pWk, g_Wk);
    cudaGetSymbolAddress(&pWv, g_Wv);   cudaGetSymbolAddress(&pWo, g_Wo);
    cudaGetSymbolAddress(&pWg, g_Wg);   cudaGetSymbolAddress(&pWu, g_Wu);
    cudaGetSymbolAddress(&pWd, g_Wd);
    cudaGetSymbolAddress(&pXn, g_Xn);   cudaGetSymbolAddress(&pQp, g_Qp);
    cudaGetSymbolAddress(&pKp, g_Kp);   cudaGetSymbolAddress(&pVh, g_Vh);
    cudaGetSymbolAddress(&pQh, g_Qh);   cudaGetSymbolAddress(&pKh, g_Kh);
    cudaGetSymbolAddress(&pAh, g_AttnH); cudaGetSymbolAddress(&pH1, g_H1);
    cudaGetSymbolAddress(&pXn2, g_Xn2); cudaGetSymbolAddress(&pGh, g_Gh);
    cudaGetSymbolAddress(&pUh, g_Uh);   cudaGetSymbolAddress(&pMh, g_Mh);

    cudaFuncSetAttribute(flash_kernel, cudaFuncAttributeMaxDynamicSharedMemorySize, FA_SMEM);
    cudaFuncSetAttribute(gemm_cp<0>, cudaFuncAttributeMaxDynamicSharedMemorySize, GEMM_SMEM);
    cudaFuncSetAttribute(gemm_cp<1>, cudaFuncAttributeMaxDynamicSharedMemorySize, GEMM_SMEM);
    cudaFuncSetAttribute(gemm_cp<2>, cudaFuncAttributeMaxDynamicSharedMemorySize, GEMM_SMEM);

    const long long nHH = (long long)HID * HID;
    const long long nIH = (long long)INTER * HID;
    const long long nSI = (long long)S_LEN * INTER;

    // 1-3: f2h q/k/v, 4: rmsnorm, 5-7: QKV GEMMs (launch 6 = gemmK captured by ncu)
    f2h_kernel<<<8192, 256>>>(wq, (__half*)pWq, nHH);
    f2h_kernel<<<8192, 256>>>(wk, (__half*)pWk, nHH);
    f2h_kernel<<<8192, 256>>>(wv, (__half*)pWv, nHH);
    rmsnorm_kernel<<<S_LEN, 256>>>(hidden, ln1, (__half*)pXn);
    gemm_cp<2><<<dim3(HID / GBN, S_LEN / GBM), 256, GEMM_SMEM>>>(
        (const __half*)pXn, (const __half*)pWq, pQp, nullptr, S_LEN, HID, HID);
    gemm_cp<2><<<dim3(HID / GBN, S_LEN / GBM), 256, GEMM_SMEM>>>(
        (const __half*)pXn, (const __half*)pWk, pKp, nullptr, S_LEN, HID, HID);
    gemm_cp<2><<<dim3(HID / GBN, S_LEN / GBM), 256, GEMM_SMEM>>>(
        (const __half*)pXn, (const __half*)pWv, pVh, nullptr, S_LEN, HID, HID);

    rope_kernel<<<(S_LEN * 2048 + 255) / 256, 256>>>(
        (const __half*)pQp, (const __half*)pKp, pos, (__half*)pQh, (__half*)pKh);
    f2h_kernel<<<8192, 256>>>(wo, (__half*)pWo, nHH);

    flash_kernel<<<dim3(S_LEN / FA_QR, NHEAD), 256, FA_SMEM>>>(
        (const __half*)pQh, (const __half*)pKh, (const __half*)pVh, (__half*)pAh);

    gemm_cp<1><<<dim3(HID / GBN, S_LEN / GBM), 256, GEMM_SMEM>>>(
        (const __half*)pAh, (const __half*)pWo, pH1, hidden, S_LEN, HID, HID);

    f2h_kernel<<<8192, 256>>>(wg, (__half*)pWg, nIH);
    f2h_kernel<<<8192, 256>>>(wu, (__half*)pWu, nIH);
    rmsnorm_kernel<<<S_LEN, 256>>>((const float*)pH1, ln2, (__half*)pXn2);
    gemm_cp<2><<<dim3(INTER / GBN, S_LEN / GBM), 256, GEMM_SMEM>>>(
        (const __half*)pXn2, (const __half*)pWg, pGh, nullptr, S_LEN, INTER, HID);
    gemm_cp<2><<<dim3(INTER / GBN, S_LEN / GBM), 256, GEMM_SMEM>>>(
        (const __half*)pXn2, (const __half*)pWu, pUh, nullptr, S_LEN, INTER, HID);
    f2h_kernel<<<8192, 256>>>(wd, (__half*)pWd, nIH);
    silu_kernel<<<4096, 256>>>((const __half*)pGh, (const __half*)pUh, (__half*)pMh, nSI);
    gemm_cp<1><<<dim3(HID / GBN, S_LEN / GBM), 256, GEMM_SMEM>>>(
        (const __half*)pMh, (const __half*)pWd, out, (const float*)pH1, S_LEN, HID, INTER);
}